// round 1
// baseline (speedup 1.0000x reference)
#include <cuda_runtime.h>
#include <math.h>

#define Bv 8
#define Cv 19
#define Hv 256
#define Wv 256
#define NPIX (Bv*Hv*Wv)

// Scratch (allocation-free rule: __device__ globals)
__device__ float g_g2[NPIX];    // squared row distance
__device__ float g_ce[NPIX];    // per-pixel cross entropy
__device__ int   g_hasb[Bv];    // per-batch "has boundary"
__device__ float g_part[Bv * (Wv/32)];  // 64 block partials

__global__ void k_init() {
    if (threadIdx.x < Bv) g_hasb[threadIdx.x] = 0;
}

// One block per (b,h) row, 256 threads (one per column).
// 1) boundary flag via 3x3 neighborhood (edge clamp)
// 2) exact 1D row distance via bidirectional doubling (8 steps)
// 3) fused CE (log-softmax over 19 channels, coalesced reads)
__global__ __launch_bounds__(256) void k_row(const float* __restrict__ x,
                                             const int*   __restrict__ tg) {
    int bh = blockIdx.x;
    int b = bh >> 8;
    int h = bh & 255;
    int j = threadIdx.x;

    __shared__ int t0[Wv], t1[Wv], t2[Wv];
    __shared__ float ds[Wv];

    const int* tb = tg + b * Hv * Wv;
    int hm = (h > 0)      ? h - 1 : 0;
    int hp = (h < Hv - 1) ? h + 1 : Hv - 1;
    t0[j] = tb[hm * Wv + j];
    t1[j] = tb[h  * Wv + j];
    t2[j] = tb[hp * Wv + j];
    __syncthreads();

    int jm = (j > 0)      ? j - 1 : 0;
    int jp = (j < Wv - 1) ? j + 1 : Wv - 1;
    int c = t1[j];
    bool bnd = (t0[jm] != c) | (t0[j] != c) | (t0[jp] != c)
             | (t1[jm] != c) | (t1[jp] != c)
             | (t2[jm] != c) | (t2[j] != c) | (t2[jp] != c);
    ds[j] = bnd ? 0.0f : 1.0e6f;   // INF matches reference cap

    // per-batch any() -> flag (int atomic: deterministic)
    if (__syncthreads_or((int)bnd)) {
        if (j == 0) atomicOr(&g_hasb[b], 1);
    }

    // Bidirectional min-plus doubling: after step s, ds[j] = min_{|k-j|<2s} f[k]+|k-j|
    #pragma unroll
    for (int s = 1; s < Wv; s <<= 1) {
        float v  = ds[j];
        float a  = (j >= s)      ? ds[j - s] + (float)s : 3.0e6f;
        float bb = (j + s < Wv)  ? ds[j + s] + (float)s : 3.0e6f;
        __syncthreads();
        ds[j] = fminf(v, fminf(a, bb));
        __syncthreads();
    }
    float r = ds[j];
    g_g2[(b * Hv + h) * Wv + j] = r * r;

    // ---- CE: log-softmax over channels (coalesced along j) ----
    const float* xb = x + ((size_t)(b * Cv) * Hv + h) * Wv + j;
    float xv[Cv];
    #pragma unroll
    for (int q = 0; q < Cv; ++q) xv[q] = xb[(size_t)q * Hv * Wv];
    float m = xv[0];
    #pragma unroll
    for (int q = 1; q < Cv; ++q) m = fmaxf(m, xv[q]);
    float s = 0.0f;
    #pragma unroll
    for (int q = 0; q < Cv; ++q) s += expf(xv[q] - m);
    float lse = m + logf(s);
    // dynamic channel index: re-read from L1 (avoids local-memory spill of xv[])
    float xt = xb[(size_t)c * Hv * Wv];
    g_ce[(b * Hv + h) * Wv + j] = lse - xt;
}

// One block per (b, 32-column tile). Exact column EDT via pruned outward scan,
// weight, multiply by CE, deterministic block reduction.
__global__ __launch_bounds__(256) void k_col() {
    __shared__ float g2s[32][Hv + 1];   // [jj][i], pad -> conflict-free
    __shared__ float red[8];

    int b  = blockIdx.x >> 3;
    int j0 = (blockIdx.x & 7) << 5;
    int tid = threadIdx.x;

    const float* g2b = g_g2 + b * Hv * Wv;
    for (int p = tid; p < 32 * Hv; p += 256) {
        int i  = p >> 5;
        int jj = p & 31;
        g2s[jj][i] = g2b[i * Wv + j0 + jj];   // coalesced 128B rows
    }
    __syncthreads();

    int hasb = g_hasb[b];
    const float* ceb = g_ce + b * Hv * Wv;
    float acc = 0.0f;

    for (int mq = 0; mq < 32; ++mq) {
        int p  = mq * 256 + tid;
        int i  = p >> 5;          // same i across a warp
        int jj = p & 31;          // jj == lane -> bank-conflict-free
        float best = g2s[jj][i];
        for (int d = 1; d < Hv; ++d) {
            float c2 = (float)(d * d);
            if (c2 >= best) break;           // exact pruning
            int lo = i - d, hi = i + d;
            if (lo >= 0) best = fminf(best, c2 + g2s[jj][lo]);
            if (hi < Hv) best = fminf(best, c2 + g2s[jj][hi]);
        }
        float w = hasb ? expf(-sqrtf(best) * 0.2f) : 1.0f;
        acc += w * ceb[i * Wv + j0 + jj];    // coalesced
    }

    // deterministic block reduce: warp shuffles then shared
    #pragma unroll
    for (int o = 16; o > 0; o >>= 1)
        acc += __shfl_down_sync(0xffffffffu, acc, o);
    if ((tid & 31) == 0) red[tid >> 5] = acc;
    __syncthreads();
    if (tid < 8) {
        float v = red[tid];
        #pragma unroll
        for (int o = 4; o > 0; o >>= 1)
            v += __shfl_down_sync(0xffu, v, o);
        if (tid == 0) g_part[blockIdx.x] = v;
    }
}

__global__ void k_final(float* __restrict__ out) {
    int t = threadIdx.x;  // 32 threads
    float v = g_part[t] + g_part[t + 32];
    #pragma unroll
    for (int o = 16; o > 0; o >>= 1)
        v += __shfl_down_sync(0xffffffffu, v, o);
    if (t == 0) out[0] = v * (1.0f / (float)NPIX);
}

extern "C" void kernel_launch(void* const* d_in, const int* in_sizes, int n_in,
                              void* d_out, int out_size) {
    const float* x  = (const float*)d_in[0];
    const int*   tg = (const int*)d_in[1];
    // robustness: pick by size (inputs has 19x more elements)
    if (n_in >= 2 && in_sizes[0] < in_sizes[1]) {
        x  = (const float*)d_in[1];
        tg = (const int*)d_in[0];
    }
    k_init<<<1, 32>>>();
    k_row<<<Bv * Hv, 256>>>(x, tg);
    k_col<<<Bv * (Wv / 32), 256>>>();
    k_final<<<1, 32>>>((float*)d_out);
}